// round 8
// baseline (speedup 1.0000x reference)
#include <cuda_runtime.h>
#include <cuda_bf16.h>
#include <math.h>
#include <stdint.h>

// Problem constants
#define BATCH 8
#define SEQ 1024
#define DIM 1024
#define NHEADS 16
#define HDIM 64
#define M_TOK (BATCH * SEQ)        // 8192
#define QKV_COLS (3 * DIM)         // 3072
#define ATT_SCALE 0.125f           // 64^-0.5

#if defined(__CUDA_ARCH__) && defined(__CUDA_ARCH_FEAT_SM103_ALL)
#define HAS_TCGEN05 1
#else
#define HAS_TCGEN05 0
#endif

// Scratch (allocation-free rule: __device__ globals)
__device__ float g_qkv[(size_t)M_TOK * QKV_COLS];        // 96 MB
__device__ float g_att[(size_t)M_TOK * DIM];             // 32 MB
__device__ float g_wt[(size_t)(QKV_COLS + DIM) * DIM];   // 16 MB: wqkvT | wprojT

// ===========================================================================
// tcgen05 helpers
// ===========================================================================
__device__ __forceinline__ uint32_t smem_u32(const void* p) {
    uint32_t a;
    asm("{ .reg .u64 t; cvta.to.shared.u64 t, %1; cvt.u32.u64 %0, t; }"
        : "=r"(a) : "l"(p));
    return a;
}

__device__ __forceinline__ uint32_t elect_one() {
    uint32_t pred;
    asm volatile(
        "{\n\t.reg .pred p;\n\t"
        "elect.sync _|p, 0xFFFFFFFF;\n\t"
        "selp.b32 %0, 1, 0, p;\n\t}"
        : "=r"(pred));
    return pred;
}

// SW128 K-major smem descriptor: layout=SW128(2), version=1, SBO=64, LBO=1
__device__ __forceinline__ uint64_t make_desc_sw128(uint32_t addr) {
    const uint64_t base =
        (uint64_t(2) << 61) | (uint64_t(1) << 46) |
        (uint64_t(64) << 32) | (uint64_t(1) << 16);
    return base | ((uint64_t)(addr >> 4) & 0x3FFF);
}

#define SWZ128(off) ((off) ^ (((off) >> 3) & 0x70))

#if HAS_TCGEN05
__device__ __forceinline__ void mma_tf32_ss(uint32_t d, uint64_t ad, uint64_t bd,
                                            uint32_t idesc, uint32_t en) {
    asm volatile(
        "{\n\t.reg .pred p;\n\t"
        "setp.ne.u32 p, %5, 0;\n\t"
        "tcgen05.mma.cta_group::1.kind::tf32 [%0], %1, %2, %3, {%4,%4,%4,%4}, p;\n\t"
        "}"
        :: "r"(d), "l"(ad), "l"(bd), "r"(idesc), "r"(0u), "r"(en)
        : "memory");
}

__device__ __forceinline__ void mma_tf32_ts(uint32_t d, uint32_t at, uint64_t bd,
                                            uint32_t idesc, uint32_t en) {
    asm volatile(
        "{\n\t.reg .pred p;\n\t"
        "setp.ne.u32 p, %5, 0;\n\t"
        "tcgen05.mma.cta_group::1.kind::tf32 [%0], [%1], %2, %3, {%4,%4,%4,%4}, p;\n\t"
        "}"
        :: "r"(d), "r"(at), "l"(bd), "r"(idesc), "r"(0u), "r"(en)
        : "memory");
}

#define TC_ALLOC(sm, n)  asm volatile("tcgen05.alloc.cta_group::1.sync.aligned.shared::cta.b32 [%0], %1;" :: "r"(sm), "r"((uint32_t)(n)) : "memory")
#define TC_DEALLOC(t, n) asm volatile("tcgen05.dealloc.cta_group::1.sync.aligned.b32 %0, %1;" :: "r"(t), "r"((uint32_t)(n)))
#define TC_RELINQ()      asm volatile("tcgen05.relinquish_alloc_permit.cta_group::1.sync.aligned;")
#define TC_COMMIT(mb)    asm volatile("tcgen05.commit.cta_group::1.mbarrier::arrive::one.shared::cluster.b64 [%0];" :: "r"(mb) : "memory")
#define TC_FENCE_BEFORE() asm volatile("tcgen05.fence::before_thread_sync;" ::: "memory")
#define TC_FENCE_AFTER() asm volatile("tcgen05.fence::after_thread_sync;" ::: "memory")
#define TC_WAIT_LD()     asm volatile("tcgen05.wait::ld.sync.aligned;" ::: "memory")
#define TC_WAIT_ST()     asm volatile("tcgen05.wait::st.sync.aligned;" ::: "memory")

#define TMEM_LDX32(r, ta)                                                   \
    asm volatile(                                                           \
        "tcgen05.ld.sync.aligned.32x32b.x32.b32 "                           \
        "{%0,%1,%2,%3,%4,%5,%6,%7,%8,%9,%10,%11,%12,%13,%14,%15,"           \
        "%16,%17,%18,%19,%20,%21,%22,%23,%24,%25,%26,%27,%28,%29,%30,%31}, [%32];" \
        : "=r"((r)[0]),"=r"((r)[1]),"=r"((r)[2]),"=r"((r)[3]),              \
          "=r"((r)[4]),"=r"((r)[5]),"=r"((r)[6]),"=r"((r)[7]),              \
          "=r"((r)[8]),"=r"((r)[9]),"=r"((r)[10]),"=r"((r)[11]),            \
          "=r"((r)[12]),"=r"((r)[13]),"=r"((r)[14]),"=r"((r)[15]),          \
          "=r"((r)[16]),"=r"((r)[17]),"=r"((r)[18]),"=r"((r)[19]),          \
          "=r"((r)[20]),"=r"((r)[21]),"=r"((r)[22]),"=r"((r)[23]),          \
          "=r"((r)[24]),"=r"((r)[25]),"=r"((r)[26]),"=r"((r)[27]),          \
          "=r"((r)[28]),"=r"((r)[29]),"=r"((r)[30]),"=r"((r)[31])           \
        : "r"(ta))

#define TMEM_LDX16(r, ta)                                                   \
    asm volatile(                                                           \
        "tcgen05.ld.sync.aligned.32x32b.x16.b32 "                           \
        "{%0,%1,%2,%3,%4,%5,%6,%7,%8,%9,%10,%11,%12,%13,%14,%15}, [%16];"   \
        : "=r"((r)[0]),"=r"((r)[1]),"=r"((r)[2]),"=r"((r)[3]),              \
          "=r"((r)[4]),"=r"((r)[5]),"=r"((r)[6]),"=r"((r)[7]),              \
          "=r"((r)[8]),"=r"((r)[9]),"=r"((r)[10]),"=r"((r)[11]),            \
          "=r"((r)[12]),"=r"((r)[13]),"=r"((r)[14]),"=r"((r)[15])           \
        : "r"(ta))

#define TMEM_STX16(ta, r)                                                   \
    asm volatile(                                                           \
        "tcgen05.st.sync.aligned.32x32b.x16.b32 [%0], "                     \
        "{%1,%2,%3,%4,%5,%6,%7,%8,%9,%10,%11,%12,%13,%14,%15,%16};"         \
        :: "r"(ta),                                                         \
           "r"((r)[0]),"r"((r)[1]),"r"((r)[2]),"r"((r)[3]),                 \
           "r"((r)[4]),"r"((r)[5]),"r"((r)[6]),"r"((r)[7]),                 \
           "r"((r)[8]),"r"((r)[9]),"r"((r)[10]),"r"((r)[11]),               \
           "r"((r)[12]),"r"((r)[13]),"r"((r)[14]),"r"((r)[15])              \
        : "memory")
#endif // HAS_TCGEN05

#define MBAR_INIT(mb, n) asm volatile("mbarrier.init.shared.b64 [%0], %1;" :: "r"(mb), "r"((uint32_t)(n)) : "memory")
#define FENCE_PROXY()    asm volatile("fence.proxy.async.shared::cta;" ::: "memory")

#define MBAR_WAIT(mb, ph) do {                                              \
    uint32_t _m = (mb), _p = (ph), _done;                                   \
    asm volatile(                                                           \
        "{\n\t.reg .pred p;\n\t"                                            \
        "mbarrier.try_wait.parity.acquire.cta.shared::cta.b64 p, [%1], %2;\n\t" \
        "selp.b32 %0, 1, 0, p;\n\t}"                                        \
        : "=r"(_done) : "r"(_m), "r"(_p) : "memory");                       \
    if (!_done) {                                                           \
        asm volatile(                                                       \
            "{\n\t.reg .pred P1;\n\t"                                       \
            "WL_%=:\n\t"                                                    \
            "mbarrier.try_wait.parity.acquire.cta.shared::cta.b64 P1, [%0], %1, 0x989680;\n\t" \
            "@P1 bra.uni WD_%=;\n\t"                                        \
            "bra.uni WL_%=;\n\t"                                            \
            "WD_%=:\n\t}"                                                   \
            :: "r"(_m), "r"(_p) : "memory");                                \
    }                                                                       \
} while (0)

__device__ __forceinline__ float f2tf32(float v) {
    unsigned int u;
    asm volatile("cvt.rna.tf32.f32 %0, %1;" : "=r"(u) : "f"(v));
    return __uint_as_float(u);
}

// ===========================================================================
// Weight pre-transpose: W[K][N] -> WT[N][K], tf32-converted. Run once/launch.
// ===========================================================================
__global__ __launch_bounds__(256) void transpose_tf32(
    const float* __restrict__ W, float* __restrict__ WT, int K, int N)
{
    __shared__ float tile[32][33];
    const int n0 = blockIdx.x * 32;
    const int k0 = blockIdx.y * 32;
    const int tx = threadIdx.x & 31;
    const int ty = threadIdx.x >> 5;

    #pragma unroll
    for (int i = ty; i < 32; i += 8)
        tile[i][tx] = W[(size_t)(k0 + i) * N + n0 + tx];
    __syncthreads();
    #pragma unroll
    for (int i = ty; i < 32; i += 8)
        WT[(size_t)(n0 + i) * K + k0 + tx] = f2tf32(tile[tx][i]);
}

// ===========================================================================
// tcgen05 tf32 GEMM (pre-transposed B): C[M,N] = A[M,K] @ BT[N,K]^T + bias[N]
// Tile 128x128, BK=32, 256 threads, double-buffered (4x16KB smem), 2 CTA/SM.
// Rows are exactly 128B -> single SW128 atom column per tile.
// ===========================================================================
#define BM 128
#define BN 128
#define GBK 32
#define GA0 0
#define GA1 16384
#define GB0 32768
#define GB1 49152
#define GEMM_SMEM 65536

__global__ __launch_bounds__(256, 2) __cluster_dims__(1, 1, 1)
void gemm_tc_tf32(const float* __restrict__ A, const float* __restrict__ BT,
                  const float* __restrict__ bias, float* __restrict__ C,
                  int M, int N, int K)
{
#if HAS_TCGEN05
    extern __shared__ __align__(1024) char dsm[];
    __shared__ uint32_t s_tmem;
    __shared__ __align__(8) uint64_t s_mbar[2];

    const int tid = threadIdx.x;
    const int brow = blockIdx.y * BM;
    const int bcol = blockIdx.x * BN;
    const uint32_t smb = smem_u32(dsm);
    const uint32_t mbar0 = smem_u32(&s_mbar[0]);
    const uint32_t mbar1 = smem_u32(&s_mbar[1]);

    if (tid < 32) TC_ALLOC(smem_u32(&s_tmem), 128);
    if (tid == 0) { MBAR_INIT(mbar0, 1); MBAR_INIT(mbar1, 1); }
    __syncthreads();
    const uint32_t tmem = s_tmem;

    const uint32_t idesc = (1u << 4) | (2u << 7) | (2u << 10)
                         | ((BN / 8) << 17) | ((BM / 16) << 24);
    const int nch = K / GBK;   // 32

    // per-thread coords: 4 float4 per operand per chunk
    int rr[4], cc[4];
    uint32_t soff[4];
    #pragma unroll
    for (int i = 0; i < 4; i++) {
        int id = i * 256 + tid;
        int r = id >> 3;             // 0..127
        int c = (id & 7) * 4;        // 0..28 floats
        rr[i] = r; cc[i] = c;
        soff[i] = SWZ128((uint32_t)(r * 128 + c * 4));
    }

    // prefetch chunk 0
    float4 av[4], bv[4];
    #pragma unroll
    for (int i = 0; i < 4; i++) {
        av[i] = *reinterpret_cast<const float4*>(
            A + (size_t)(brow + rr[i]) * K + cc[i]);
        bv[i] = *reinterpret_cast<const float4*>(
            BT + (size_t)(bcol + rr[i]) * K + cc[i]);
    }

    for (int ch = 0; ch < nch; ch++) {
        const int b = ch & 1;
        const uint32_t abuf = smb + (b ? GA1 : GA0);
        const uint32_t bbuf = smb + (b ? GB1 : GB0);

        if (ch >= 2) MBAR_WAIT(b ? mbar1 : mbar0, ((ch >> 1) - 1) & 1);

        #pragma unroll
        for (int i = 0; i < 4; i++) {
            asm volatile("st.shared.v4.b32 [%0], {%1,%2,%3,%4};"
                :: "r"(abuf + soff[i]),
                   "r"(__float_as_uint(f2tf32(av[i].x))),
                   "r"(__float_as_uint(f2tf32(av[i].y))),
                   "r"(__float_as_uint(f2tf32(av[i].z))),
                   "r"(__float_as_uint(f2tf32(av[i].w))) : "memory");
            asm volatile("st.shared.v4.b32 [%0], {%1,%2,%3,%4};"
                :: "r"(bbuf + soff[i]),
                   "r"(__float_as_uint(bv[i].x)), "r"(__float_as_uint(bv[i].y)),
                   "r"(__float_as_uint(bv[i].z)), "r"(__float_as_uint(bv[i].w))
                : "memory");
        }

        if (ch + 1 < nch) {
            const int k0 = (ch + 1) * GBK;
            #pragma unroll
            for (int i = 0; i < 4; i++) {
                av[i] = *reinterpret_cast<const float4*>(
                    A + (size_t)(brow + rr[i]) * K + k0 + cc[i]);
                bv[i] = *reinterpret_cast<const float4*>(
                    BT + (size_t)(bcol + rr[i]) * K + k0 + cc[i]);
            }
        }

        FENCE_PROXY();
        __syncthreads();

        if (tid < 32) {
            if (elect_one()) {
                uint64_t ad = make_desc_sw128(abuf);
                uint64_t bd = make_desc_sw128(bbuf);
                #pragma unroll
                for (int s = 0; s < 4; s++)
                    mma_tf32_ss(tmem, ad + 2 * s, bd + 2 * s, idesc,
                                (ch | s) != 0);
                TC_COMMIT(b ? mbar1 : mbar0);
            }
        }
    }

    {
        const int last = nch - 1;
        MBAR_WAIT((last & 1) ? mbar1 : mbar0, (last >> 1) & 1);
    }
    TC_FENCE_AFTER();

    if (tid < 128) {
        const int wid = tid >> 5;
        const int lane = tid & 31;
        const int row = brow + wid * 32 + lane;
        #pragma unroll
        for (int c0 = 0; c0 < BN; c0 += 32) {
            uint32_t d[32];
            TMEM_LDX32(d, tmem + c0);
            TC_WAIT_LD();
            #pragma unroll
            for (int c = 0; c < 32; c += 4) {
                float4 v;
                v.x = __uint_as_float(d[c + 0]) + bias[bcol + c0 + c + 0];
                v.y = __uint_as_float(d[c + 1]) + bias[bcol + c0 + c + 1];
                v.z = __uint_as_float(d[c + 2]) + bias[bcol + c0 + c + 2];
                v.w = __uint_as_float(d[c + 3]) + bias[bcol + c0 + c + 3];
                *reinterpret_cast<float4*>(C + (size_t)row * N + bcol + c0 + c) = v;
            }
        }
    }
    __syncthreads();
    if (tid < 32) {
        TC_RELINQ();
        TC_DEALLOC(tmem, 128);
    }
#endif // HAS_TCGEN05
}

// ===========================================================================
// Tensor-core flash attention (tf32, no online max).
// One CTA = (b, h, 128-query tile), 256 threads, 8 KV tiles of 128 keys.
// TMEM (256 cols, 2 CTA/SM): S/P in-place cols [0,128), O cols [128,192).
// SMEM 96KB: Q 32K | K 32K | Vt 32K.
// ===========================================================================
#define AQ_OFF 0
#define AK_OFF 32768
#define AV_OFF 65536
#define ATT_SMEM 98304

__global__ __launch_bounds__(256, 2) __cluster_dims__(1, 1, 1)
void attn_tc(const float* __restrict__ qkv, float* __restrict__ out)
{
#if HAS_TCGEN05
    extern __shared__ __align__(1024) char dsm[];
    __shared__ uint32_t s_tmem;
    __shared__ __align__(8) uint64_t s_mb[2];

    const int tid = threadIdx.x;
    const int qt = blockIdx.x;
    const int h  = blockIdx.y;
    const int b  = blockIdx.z;
    const uint32_t smb = smem_u32(dsm);
    const uint32_t mb_s = smem_u32(&s_mb[0]);
    const uint32_t mb_o = smem_u32(&s_mb[1]);

    if (tid < 32) TC_ALLOC(smem_u32(&s_tmem), 256);
    if (tid == 0) { MBAR_INIT(mb_s, 1); MBAR_INIT(mb_o, 1); }
    __syncthreads();
    const uint32_t tmem = s_tmem;
    const uint32_t TS = tmem;            // S cols [0,128); P written in place
    const uint32_t TO = tmem + 128;      // O cols [128,192)

    const size_t tokQ = (size_t)b * SEQ + qt * 128;
    const size_t tokB = (size_t)b * SEQ;

    const uint32_t idescS = (1u << 4) | (2u << 7) | (2u << 10)
                          | (16u << 17) | (8u << 24);
    const uint32_t idescO = (1u << 4) | (2u << 7) | (2u << 10)
                          | (8u << 17) | (8u << 24);

    #pragma unroll
    for (int i = 0; i < 8; i++) {
        int id = i * 256 + tid;
        int r  = id >> 4;
        int cq = (id & 15) * 4;
        float4 v = *reinterpret_cast<const float4*>(
            qkv + (tokQ + r) * QKV_COLS + h * HDIM + cq);
        uint32_t x0 = __float_as_uint(f2tf32(v.x * ATT_SCALE));
        uint32_t x1 = __float_as_uint(f2tf32(v.y * ATT_SCALE));
        uint32_t x2 = __float_as_uint(f2tf32(v.z * ATT_SCALE));
        uint32_t x3 = __float_as_uint(f2tf32(v.w * ATT_SCALE));
        uint32_t off = AQ_OFF + (cq >> 5) * 16384
                     + SWZ128((uint32_t)(r * 128 + (cq & 31) * 4));
        asm volatile("st.shared.v4.b32 [%0], {%1,%2,%3,%4};"
            :: "r"(smb + off), "r"(x0), "r"(x1), "r"(x2), "r"(x3) : "memory");
    }

    float lsum = 0.f;

    for (int t = 0; t < 8; t++) {
        // O-MMA(t-1) reads P (TMEM cols [0,128)) and V smem: wait before
        // S-MMA(t) / the K,V loads below overwrite them.
        if (t > 0) MBAR_WAIT(mb_o, (t - 1) & 1);

        #pragma unroll
        for (int i = 0; i < 8; i++) {
            int id = i * 256 + tid;
            int r  = id >> 4;
            int cq = (id & 15) * 4;
            float4 v = *reinterpret_cast<const float4*>(
                qkv + (tokB + t * 128 + r) * QKV_COLS + DIM + h * HDIM + cq);
            uint32_t x0 = __float_as_uint(f2tf32(v.x));
            uint32_t x1 = __float_as_uint(f2tf32(v.y));
            uint32_t x2 = __float_as_uint(f2tf32(v.z));
            uint32_t x3 = __float_as_uint(f2tf32(v.w));
            uint32_t off = AK_OFF + (cq >> 5) * 16384
                         + SWZ128((uint32_t)(r * 128 + (cq & 31) * 4));
            asm volatile("st.shared.v4.b32 [%0], {%1,%2,%3,%4};"
                :: "r"(smb + off), "r"(x0), "r"(x1), "r"(x2), "r"(x3) : "memory");
        }

        #pragma unroll
        for (int i = 0; i < 8; i++) {
            int id  = i * 256 + tid;
            int key = id >> 4;
            int dq  = (id & 15) * 4;
            float4 v = *reinterpret_cast<const float4*>(
                qkv + (tokB + t * 128 + key) * QKV_COLS + 2 * DIM + h * HDIM + dq);
            uint32_t kb  = (key >> 5) * 8192;
            uint32_t kc4 = (key & 31) * 4;
            uint32_t o0 = AV_OFF + kb + SWZ128((uint32_t)((dq + 0) * 128 + kc4));
            uint32_t o1 = AV_OFF + kb + SWZ128((uint32_t)((dq + 1) * 128 + kc4));
            uint32_t o2 = AV_OFF + kb + SWZ128((uint32_t)((dq + 2) * 128 + kc4));
            uint32_t o3 = AV_OFF + kb + SWZ128((uint32_t)((dq + 3) * 128 + kc4));
            asm volatile("st.shared.b32 [%0], %1;" :: "r"(smb + o0),
                         "r"(__float_as_uint(f2tf32(v.x))) : "memory");
            asm volatile("st.shared.b32 [%0], %1;" :: "r"(smb + o1),
                         "r"(__float_as_uint(f2tf32(v.y))) : "memory");
            asm volatile("st.shared.b32 [%0], %1;" :: "r"(smb + o2),
                         "r"(__float_as_uint(f2tf32(v.z))) : "memory");
            asm volatile("st.shared.b32 [%0], %1;" :: "r"(smb + o3),
                         "r"(__float_as_uint(f2tf32(v.w))) : "memory");
        }
        FENCE_PROXY();
        __syncthreads();

        if (tid < 32) {
            if (elect_one()) {
                #pragma unroll
                for (int s = 0; s < 8; s++) {
                    uint64_t ad = make_desc_sw128(smb + AQ_OFF + (s >> 2) * 16384)
                                + (uint64_t)(s & 3) * 2;
                    uint64_t bd = make_desc_sw128(smb + AK_OFF + (s >> 2) * 16384)
                                + (uint64_t)(s & 3) * 2;
                    mma_tf32_ss(TS, ad, bd, idescS, s != 0);
                }
                TC_COMMIT(mb_s);
            }
        }

        // softmax: P overwrites S in place (x16 chunks, low reg pressure)
        if (tid < 128) {
            MBAR_WAIT(mb_s, t & 1);
            TC_FENCE_AFTER();
            const uint32_t woff = (uint32_t)(tid >> 5) << 21;
            #pragma unroll
            for (int cc = 0; cc < 8; cc++) {
                uint32_t sr[16];
                TMEM_LDX16(sr, TS + cc * 16);
                TC_WAIT_LD();
                #pragma unroll
                for (int k = 0; k < 16; k++) {
                    float p = __expf(__uint_as_float(sr[k]));
                    lsum += p;
                    sr[k] = __float_as_uint(f2tf32(p));
                }
                TMEM_STX16(TS + cc * 16 + woff, sr);
            }
            TC_WAIT_ST();
            TC_FENCE_BEFORE();
        }
        __syncthreads();

        if (tid < 32) {
            if (elect_one()) {
                TC_FENCE_AFTER();
                #pragma unroll
                for (int s = 0; s < 16; s++) {
                    uint64_t bd = make_desc_sw128(smb + AV_OFF + (s >> 2) * 8192)
                                + (uint64_t)(s & 3) * 2;
                    mma_tf32_ts(TO, TS + s * 8, bd, idescO, (t | s) != 0);
                }
                TC_COMMIT(mb_o);
            }
        }
        __syncthreads();
    }

    if (tid < 128) {
        MBAR_WAIT(mb_o, 7 & 1);
        TC_FENCE_AFTER();
        const float inv = 1.f / lsum;
        float* op = out + (tokQ + tid) * (size_t)DIM + h * HDIM;
        #pragma unroll
        for (int cc = 0; cc < 4; cc++) {
            uint32_t orr[16];
            TMEM_LDX16(orr, TO + cc * 16);
            TC_WAIT_LD();
            #pragma unroll
            for (int c = 0; c < 16; c += 4) {
                float4 v;
                v.x = __uint_as_float(orr[c + 0]) * inv;
                v.y = __uint_as_float(orr[c + 1]) * inv;
                v.z = __uint_as_float(orr[c + 2]) * inv;
                v.w = __uint_as_float(orr[c + 3]) * inv;
                *reinterpret_cast<float4*>(op + cc * 16 + c) = v;
            }
        }
    }
    __syncthreads();
    if (tid < 32) {
        TC_RELINQ();
        TC_DEALLOC(tmem, 256);
    }
#endif // HAS_TCGEN05
}

// ---------------------------------------------------------------------------
extern "C" void kernel_launch(void* const* d_in, const int* in_sizes, int n_in,
                              void* d_out, int out_size)
{
    const float* inp    = (const float*)d_in[0];   // [8,1024,1024]
    const float* w_qkv  = (const float*)d_in[1];   // [1024,3072]
    const float* b_qkv  = (const float*)d_in[2];   // [3072]
    const float* w_proj = (const float*)d_in[3];   // [1024,1024]
    const float* b_proj = (const float*)d_in[4];   // [1024]
    float* out = (float*)d_out;                    // [8,1024,1024]

    float *qkv_ptr, *att_ptr, *wt_ptr;
    cudaGetSymbolAddress((void**)&qkv_ptr, g_qkv);
    cudaGetSymbolAddress((void**)&att_ptr, g_att);
    cudaGetSymbolAddress((void**)&wt_ptr,  g_wt);
    float* wqkvT  = wt_ptr;                           // [3072][1024]
    float* wprojT = wt_ptr + (size_t)QKV_COLS * DIM;  // [1024][1024]

    cudaFuncSetAttribute(gemm_tc_tf32,
                         cudaFuncAttributeMaxDynamicSharedMemorySize,
                         GEMM_SMEM);
    cudaFuncSetAttribute(attn_tc,
                         cudaFuncAttributeMaxDynamicSharedMemorySize,
                         ATT_SMEM);

    // 0) pre-transpose weights to [N][K] tf32
    {
        dim3 g1(QKV_COLS / 32, DIM / 32);
        transpose_tf32<<<g1, 256>>>(w_qkv, wqkvT, DIM, QKV_COLS);
        dim3 g2(DIM / 32, DIM / 32);
        transpose_tf32<<<g2, 256>>>(w_proj, wprojT, DIM, DIM);
    }
    // 1) QKV GEMM
    {
        dim3 grid(QKV_COLS / BN, M_TOK / BM);
        gemm_tc_tf32<<<grid, 256, GEMM_SMEM>>>(inp, wqkvT, b_qkv, qkv_ptr,
                                               M_TOK, QKV_COLS, DIM);
    }
    // 2) attention
    {
        dim3 grid(SEQ / 128, NHEADS, BATCH);
        attn_tc<<<grid, 256, ATT_SMEM>>>(qkv_ptr, att_ptr);
    }
    // 3) projection
    {
        dim3 grid(DIM / BN, M_TOK / BM);
        gemm_tc_tf32<<<grid, 256, GEMM_SMEM>>>(att_ptr, wprojT, b_proj, out,
                                               M_TOK, DIM, DIM);
    }
}

// round 10
// speedup vs baseline: 1.3344x; 1.3344x over previous
#include <cuda_runtime.h>
#include <cuda_bf16.h>
#include <math.h>
#include <stdint.h>

// Problem constants
#define BATCH 8
#define SEQ 1024
#define DIM 1024
#define NHEADS 16
#define HDIM 64
#define M_TOK (BATCH * SEQ)        // 8192
#define QKV_COLS (3 * DIM)         // 3072
#define ATT_SCALE 0.125f           // 64^-0.5

#if defined(__CUDA_ARCH__) && defined(__CUDA_ARCH_FEAT_SM103_ALL)
#define HAS_TCGEN05 1
#else
#define HAS_TCGEN05 0
#endif

// Scratch (allocation-free rule: __device__ globals)
__device__ float g_qkv[(size_t)M_TOK * QKV_COLS];        // 96 MB
__device__ float g_att[(size_t)M_TOK * DIM];             // 32 MB
__device__ float g_wt[(size_t)(QKV_COLS + DIM) * DIM];   // 16 MB: wqkvT | wprojT

// ===========================================================================
// tcgen05 helpers
// ===========================================================================
__device__ __forceinline__ uint32_t smem_u32(const void* p) {
    uint32_t a;
    asm("{ .reg .u64 t; cvta.to.shared.u64 t, %1; cvt.u32.u64 %0, t; }"
        : "=r"(a) : "l"(p));
    return a;
}

__device__ __forceinline__ uint32_t elect_one() {
    uint32_t pred;
    asm volatile(
        "{\n\t.reg .pred p;\n\t"
        "elect.sync _|p, 0xFFFFFFFF;\n\t"
        "selp.b32 %0, 1, 0, p;\n\t}"
        : "=r"(pred));
    return pred;
}

// SW128 K-major smem descriptor: layout=SW128(2), version=1, SBO=64, LBO=1
__device__ __forceinline__ uint64_t make_desc_sw128(uint32_t addr) {
    const uint64_t base =
        (uint64_t(2) << 61) | (uint64_t(1) << 46) |
        (uint64_t(64) << 32) | (uint64_t(1) << 16);
    return base | ((uint64_t)(addr >> 4) & 0x3FFF);
}

#define SWZ128(off) ((off) ^ (((off) >> 3) & 0x70))

#if HAS_TCGEN05
__device__ __forceinline__ void mma_tf32_ss(uint32_t d, uint64_t ad, uint64_t bd,
                                            uint32_t idesc, uint32_t en) {
    asm volatile(
        "{\n\t.reg .pred p;\n\t"
        "setp.ne.u32 p, %5, 0;\n\t"
        "tcgen05.mma.cta_group::1.kind::tf32 [%0], %1, %2, %3, {%4,%4,%4,%4}, p;\n\t"
        "}"
        :: "r"(d), "l"(ad), "l"(bd), "r"(idesc), "r"(0u), "r"(en)
        : "memory");
}

__device__ __forceinline__ void mma_tf32_ts(uint32_t d, uint32_t at, uint64_t bd,
                                            uint32_t idesc, uint32_t en) {
    asm volatile(
        "{\n\t.reg .pred p;\n\t"
        "setp.ne.u32 p, %5, 0;\n\t"
        "tcgen05.mma.cta_group::1.kind::tf32 [%0], [%1], %2, %3, {%4,%4,%4,%4}, p;\n\t"
        "}"
        :: "r"(d), "r"(at), "l"(bd), "r"(idesc), "r"(0u), "r"(en)
        : "memory");
}

#define TC_ALLOC(sm, n)  asm volatile("tcgen05.alloc.cta_group::1.sync.aligned.shared::cta.b32 [%0], %1;" :: "r"(sm), "r"((uint32_t)(n)) : "memory")
#define TC_DEALLOC(t, n) asm volatile("tcgen05.dealloc.cta_group::1.sync.aligned.b32 %0, %1;" :: "r"(t), "r"((uint32_t)(n)))
#define TC_RELINQ()      asm volatile("tcgen05.relinquish_alloc_permit.cta_group::1.sync.aligned;")
#define TC_COMMIT(mb)    asm volatile("tcgen05.commit.cta_group::1.mbarrier::arrive::one.shared::cluster.b64 [%0];" :: "r"(mb) : "memory")
#define TC_FENCE_BEFORE() asm volatile("tcgen05.fence::before_thread_sync;" ::: "memory")
#define TC_FENCE_AFTER() asm volatile("tcgen05.fence::after_thread_sync;" ::: "memory")
#define TC_WAIT_LD()     asm volatile("tcgen05.wait::ld.sync.aligned;" ::: "memory")
#define TC_WAIT_ST()     asm volatile("tcgen05.wait::st.sync.aligned;" ::: "memory")

#define TMEM_LDX32(r, ta)                                                   \
    asm volatile(                                                           \
        "tcgen05.ld.sync.aligned.32x32b.x32.b32 "                           \
        "{%0,%1,%2,%3,%4,%5,%6,%7,%8,%9,%10,%11,%12,%13,%14,%15,"           \
        "%16,%17,%18,%19,%20,%21,%22,%23,%24,%25,%26,%27,%28,%29,%30,%31}, [%32];" \
        : "=r"((r)[0]),"=r"((r)[1]),"=r"((r)[2]),"=r"((r)[3]),              \
          "=r"((r)[4]),"=r"((r)[5]),"=r"((r)[6]),"=r"((r)[7]),              \
          "=r"((r)[8]),"=r"((r)[9]),"=r"((r)[10]),"=r"((r)[11]),            \
          "=r"((r)[12]),"=r"((r)[13]),"=r"((r)[14]),"=r"((r)[15]),          \
          "=r"((r)[16]),"=r"((r)[17]),"=r"((r)[18]),"=r"((r)[19]),          \
          "=r"((r)[20]),"=r"((r)[21]),"=r"((r)[22]),"=r"((r)[23]),          \
          "=r"((r)[24]),"=r"((r)[25]),"=r"((r)[26]),"=r"((r)[27]),          \
          "=r"((r)[28]),"=r"((r)[29]),"=r"((r)[30]),"=r"((r)[31])           \
        : "r"(ta))

#define TMEM_STX32(ta, r)                                                   \
    asm volatile(                                                           \
        "tcgen05.st.sync.aligned.32x32b.x32.b32 [%0], "                     \
        "{%1,%2,%3,%4,%5,%6,%7,%8,%9,%10,%11,%12,%13,%14,%15,%16,"          \
        "%17,%18,%19,%20,%21,%22,%23,%24,%25,%26,%27,%28,%29,%30,%31,%32};" \
        :: "r"(ta),                                                         \
           "r"((r)[0]),"r"((r)[1]),"r"((r)[2]),"r"((r)[3]),                 \
           "r"((r)[4]),"r"((r)[5]),"r"((r)[6]),"r"((r)[7]),                 \
           "r"((r)[8]),"r"((r)[9]),"r"((r)[10]),"r"((r)[11]),               \
           "r"((r)[12]),"r"((r)[13]),"r"((r)[14]),"r"((r)[15]),             \
           "r"((r)[16]),"r"((r)[17]),"r"((r)[18]),"r"((r)[19]),             \
           "r"((r)[20]),"r"((r)[21]),"r"((r)[22]),"r"((r)[23]),             \
           "r"((r)[24]),"r"((r)[25]),"r"((r)[26]),"r"((r)[27]),             \
           "r"((r)[28]),"r"((r)[29]),"r"((r)[30]),"r"((r)[31])              \
        : "memory")
#endif // HAS_TCGEN05

#define MBAR_INIT(mb, n) asm volatile("mbarrier.init.shared.b64 [%0], %1;" :: "r"(mb), "r"((uint32_t)(n)) : "memory")
#define FENCE_PROXY()    asm volatile("fence.proxy.async.shared::cta;" ::: "memory")

#define MBAR_WAIT(mb, ph) do {                                              \
    uint32_t _m = (mb), _p = (ph), _done;                                   \
    asm volatile(                                                           \
        "{\n\t.reg .pred p;\n\t"                                            \
        "mbarrier.try_wait.parity.acquire.cta.shared::cta.b64 p, [%1], %2;\n\t" \
        "selp.b32 %0, 1, 0, p;\n\t}"                                        \
        : "=r"(_done) : "r"(_m), "r"(_p) : "memory");                       \
    if (!_done) {                                                           \
        asm volatile(                                                       \
            "{\n\t.reg .pred P1;\n\t"                                       \
            "WL_%=:\n\t"                                                    \
            "mbarrier.try_wait.parity.acquire.cta.shared::cta.b64 P1, [%0], %1, 0x989680;\n\t" \
            "@P1 bra.uni WD_%=;\n\t"                                        \
            "bra.uni WL_%=;\n\t"                                            \
            "WD_%=:\n\t}"                                                   \
            :: "r"(_m), "r"(_p) : "memory");                                \
    }                                                                       \
} while (0)

__device__ __forceinline__ float f2tf32(float v) {
    unsigned int u;
    asm volatile("cvt.rna.tf32.f32 %0, %1;" : "=r"(u) : "f"(v));
    return __uint_as_float(u);
}

// ===========================================================================
// Weight pre-transpose: W[K][N] -> WT[N][K], tf32-converted. Run once/launch.
// ===========================================================================
__global__ __launch_bounds__(256) void transpose_tf32(
    const float* __restrict__ W, float* __restrict__ WT, int K, int N)
{
    __shared__ float tile[32][33];
    const int n0 = blockIdx.x * 32;
    const int k0 = blockIdx.y * 32;
    const int tx = threadIdx.x & 31;
    const int ty = threadIdx.x >> 5;

    #pragma unroll
    for (int i = ty; i < 32; i += 8)
        tile[i][tx] = W[(size_t)(k0 + i) * N + n0 + tx];
    __syncthreads();
    #pragma unroll
    for (int i = ty; i < 32; i += 8)
        WT[(size_t)(n0 + i) * K + k0 + tx] = f2tf32(tile[tx][i]);
}

// ===========================================================================
// tcgen05 tf32 GEMM (pre-transposed B) — round-7 configuration (BK=64).
// Tile 128x128, 256 threads, double-buffered, register prefetch.
// Blocked SW128 atom layout: rows of 64 floats = 2 atom cols; 16 atom-rows
// per col -> atom-col stride 16384B. K-step offsets: 2s (s<4), 1024+2(s-4).
// ===========================================================================
#define BM 128
#define BN 128
#define GBK 64
#define GA0 0
#define GA1 32768
#define GB0 65536
#define GB1 98304
#define GEMM_SMEM 131072

__global__ __launch_bounds__(256, 1) __cluster_dims__(1, 1, 1)
void gemm_tc_tf32(const float* __restrict__ A, const float* __restrict__ BT,
                  const float* __restrict__ bias, float* __restrict__ C,
                  int M, int N, int K)
{
#if HAS_TCGEN05
    extern __shared__ __align__(1024) char dsm[];
    __shared__ uint32_t s_tmem;
    __shared__ __align__(8) uint64_t s_mbar[2];

    const int tid = threadIdx.x;
    const int brow = blockIdx.y * BM;
    const int bcol = blockIdx.x * BN;
    const uint32_t smb = smem_u32(dsm);
    const uint32_t mbar0 = smem_u32(&s_mbar[0]);
    const uint32_t mbar1 = smem_u32(&s_mbar[1]);

    if (tid < 32) TC_ALLOC(smem_u32(&s_tmem), 128);
    if (tid == 0) { MBAR_INIT(mbar0, 1); MBAR_INIT(mbar1, 1); }
    __syncthreads();
    const uint32_t tmem = s_tmem;

    const uint32_t idesc = (1u << 4) | (2u << 7) | (2u << 10)
                         | ((BN / 8) << 17) | ((BM / 16) << 24);
    const int nch = K / GBK;   // 16

    int rr[8], cc[8];
    uint32_t soff[8];
    #pragma unroll
    for (int i = 0; i < 8; i++) {
        int id = i * 256 + tid;
        int r = id >> 4;
        int c = (id & 15) * 4;
        rr[i] = r; cc[i] = c;
        uint32_t off = (uint32_t)(((c >> 5) * 16 + (r >> 3)) * 1024
                                  + (r & 7) * 128 + (c & 31) * 4);
        soff[i] = SWZ128(off);
    }

    float4 av[8], bv[8];
    #pragma unroll
    for (int i = 0; i < 8; i++) {
        av[i] = *reinterpret_cast<const float4*>(
            A + (size_t)(brow + rr[i]) * K + cc[i]);
        bv[i] = *reinterpret_cast<const float4*>(
            BT + (size_t)(bcol + rr[i]) * K + cc[i]);
    }

    for (int ch = 0; ch < nch; ch++) {
        const int b = ch & 1;
        const uint32_t abuf = smb + (b ? GA1 : GA0);
        const uint32_t bbuf = smb + (b ? GB1 : GB0);

        if (ch >= 2) MBAR_WAIT(b ? mbar1 : mbar0, ((ch >> 1) - 1) & 1);

        #pragma unroll
        for (int i = 0; i < 8; i++) {
            asm volatile("st.shared.v4.b32 [%0], {%1,%2,%3,%4};"
                :: "r"(abuf + soff[i]),
                   "r"(__float_as_uint(f2tf32(av[i].x))),
                   "r"(__float_as_uint(f2tf32(av[i].y))),
                   "r"(__float_as_uint(f2tf32(av[i].z))),
                   "r"(__float_as_uint(f2tf32(av[i].w))) : "memory");
            asm volatile("st.shared.v4.b32 [%0], {%1,%2,%3,%4};"
                :: "r"(bbuf + soff[i]),
                   "r"(__float_as_uint(bv[i].x)), "r"(__float_as_uint(bv[i].y)),
                   "r"(__float_as_uint(bv[i].z)), "r"(__float_as_uint(bv[i].w))
                : "memory");
        }

        if (ch + 1 < nch) {
            const int k0 = (ch + 1) * GBK;
            #pragma unroll
            for (int i = 0; i < 8; i++) {
                av[i] = *reinterpret_cast<const float4*>(
                    A + (size_t)(brow + rr[i]) * K + k0 + cc[i]);
                bv[i] = *reinterpret_cast<const float4*>(
                    BT + (size_t)(bcol + rr[i]) * K + k0 + cc[i]);
            }
        }

        FENCE_PROXY();
        __syncthreads();

        if (tid < 32) {
            if (elect_one()) {
                uint64_t ad = make_desc_sw128(abuf);
                uint64_t bd = make_desc_sw128(bbuf);
                #pragma unroll
                for (int s = 0; s < 8; s++) {
                    uint64_t dso = (uint64_t)((s & 3) * 2 + (s >> 2) * 1024);
                    mma_tf32_ss(tmem, ad + dso, bd + dso, idesc, (ch | s) != 0);
                }
                TC_COMMIT(b ? mbar1 : mbar0);
            }
        }
    }

    {
        const int last = nch - 1;
        MBAR_WAIT((last & 1) ? mbar1 : mbar0, (last >> 1) & 1);
    }
    TC_FENCE_AFTER();

    if (tid < 128) {
        const int wid = tid >> 5;
        const int lane = tid & 31;
        const int row = brow + wid * 32 + lane;
        #pragma unroll
        for (int c0 = 0; c0 < BN; c0 += 32) {
            uint32_t d[32];
            TMEM_LDX32(d, tmem + c0);
            TC_WAIT_LD();
            #pragma unroll
            for (int c = 0; c < 32; c += 4) {
                float4 v;
                v.x = __uint_as_float(d[c + 0]) + bias[bcol + c0 + c + 0];
                v.y = __uint_as_float(d[c + 1]) + bias[bcol + c0 + c + 1];
                v.z = __uint_as_float(d[c + 2]) + bias[bcol + c0 + c + 2];
                v.w = __uint_as_float(d[c + 3]) + bias[bcol + c0 + c + 3];
                *reinterpret_cast<float4*>(C + (size_t)row * N + bcol + c0 + c) = v;
            }
        }
    }
    __syncthreads();
    if (tid < 32) {
        TC_RELINQ();
        TC_DEALLOC(tmem, 128);
    }
#endif // HAS_TCGEN05
}

// ===========================================================================
// Tensor-core flash attention (tf32, no online max), intra-CTA pipelined.
// One CTA = (b, h, 128-query tile), 256 threads, 8 KV tiles of 128 keys.
// Double-buffered K/V smem; KV(t+1) prefetched to regs during tile t compute.
// TMEM (256 cols): S/P in place cols [0,128), O cols [128,192).
// SMEM 160KB: Q 32K | K0 32K | K1 32K | Vt0 32K | Vt1 32K.
// ===========================================================================
#define AQ_OFF 0
#define AK_OFF(buf) (32768 + (buf) * 32768)
#define AV_OFF(buf) (98304 + (buf) * 32768)
#define ATT_SMEM 163840

__global__ __launch_bounds__(256, 1) __cluster_dims__(1, 1, 1)
void attn_tc(const float* __restrict__ qkv, float* __restrict__ out)
{
#if HAS_TCGEN05
    extern __shared__ __align__(1024) char dsm[];
    __shared__ uint32_t s_tmem;
    __shared__ __align__(8) uint64_t s_mb[2];

    const int tid = threadIdx.x;
    const int qt = blockIdx.x;
    const int h  = blockIdx.y;
    const int b  = blockIdx.z;
    const uint32_t smb = smem_u32(dsm);
    const uint32_t mb_s = smem_u32(&s_mb[0]);
    const uint32_t mb_o = smem_u32(&s_mb[1]);

    if (tid < 32) TC_ALLOC(smem_u32(&s_tmem), 256);
    if (tid == 0) { MBAR_INIT(mb_s, 1); MBAR_INIT(mb_o, 1); }
    __syncthreads();
    const uint32_t tmem = s_tmem;
    const uint32_t TS = tmem;            // S cols [0,128); P in place
    const uint32_t TO = tmem + 128;      // O cols [128,192)

    const size_t tokQ = (size_t)b * SEQ + qt * 128;
    const size_t tokB = (size_t)b * SEQ;

    const uint32_t idescS = (1u << 4) | (2u << 7) | (2u << 10)
                          | (16u << 17) | (8u << 24);
    const uint32_t idescO = (1u << 4) | (2u << 7) | (2u << 10)
                          | (8u << 17) | (8u << 24);

    // per-thread load coords (shared by Q/K row-major and V transpose)
    int rI[8], cI[8];
    #pragma unroll
    for (int i = 0; i < 8; i++) {
        int id = i * 256 + tid;
        rI[i] = id >> 4;            // row/key 0..127
        cI[i] = (id & 15) * 4;      // dim 0..60
    }

    // ---- Q tile -> smem (scaled, tf32) ----
    #pragma unroll
    for (int i = 0; i < 8; i++) {
        float4 v = *reinterpret_cast<const float4*>(
            qkv + (tokQ + rI[i]) * QKV_COLS + h * HDIM + cI[i]);
        uint32_t off = AQ_OFF + (cI[i] >> 5) * 16384
                     + SWZ128((uint32_t)(rI[i] * 128 + (cI[i] & 31) * 4));
        asm volatile("st.shared.v4.b32 [%0], {%1,%2,%3,%4};"
            :: "r"(smb + off),
               "r"(__float_as_uint(f2tf32(v.x * ATT_SCALE))),
               "r"(__float_as_uint(f2tf32(v.y * ATT_SCALE))),
               "r"(__float_as_uint(f2tf32(v.z * ATT_SCALE))),
               "r"(__float_as_uint(f2tf32(v.w * ATT_SCALE))) : "memory");
    }

    // ---- prefetch KV tile 0 into registers ----
    float4 kreg[8], vreg[8];
    #pragma unroll
    for (int i = 0; i < 8; i++) {
        const float* base = qkv + (tokB + rI[i]) * QKV_COLS + h * HDIM + cI[i];
        kreg[i] = *reinterpret_cast<const float4*>(base + DIM);
        vreg[i] = *reinterpret_cast<const float4*>(base + 2 * DIM);
    }

    float lsum = 0.f;

    for (int t = 0; t < 8; t++) {
        const int buf = t & 1;
        // O-MMA(t-1) reads P (TS cols) and V buffer `buf`: wait first.
        if (t > 0) MBAR_WAIT(mb_o, (t - 1) & 1);

        // ---- store prefetched K/V regs into smem buffer `buf` ----
        #pragma unroll
        for (int i = 0; i < 8; i++) {
            uint32_t koff = AK_OFF(buf) + (cI[i] >> 5) * 16384
                          + SWZ128((uint32_t)(rI[i] * 128 + (cI[i] & 31) * 4));
            asm volatile("st.shared.v4.b32 [%0], {%1,%2,%3,%4};"
                :: "r"(smb + koff),
                   "r"(__float_as_uint(f2tf32(kreg[i].x))),
                   "r"(__float_as_uint(f2tf32(kreg[i].y))),
                   "r"(__float_as_uint(f2tf32(kreg[i].z))),
                   "r"(__float_as_uint(f2tf32(kreg[i].w))) : "memory");
            // V transposed scatter: Vt[dim][key]
            uint32_t kb  = (rI[i] >> 5) * 8192;
            uint32_t kc4 = (rI[i] & 31) * 4;
            uint32_t o0 = AV_OFF(buf) + kb + SWZ128((uint32_t)((cI[i] + 0) * 128 + kc4));
            uint32_t o1 = AV_OFF(buf) + kb + SWZ128((uint32_t)((cI[i] + 1) * 128 + kc4));
            uint32_t o2 = AV_OFF(buf) + kb + SWZ128((uint32_t)((cI[i] + 2) * 128 + kc4));
            uint32_t o3 = AV_OFF(buf) + kb + SWZ128((uint32_t)((cI[i] + 3) * 128 + kc4));
            asm volatile("st.shared.b32 [%0], %1;" :: "r"(smb + o0),
                         "r"(__float_as_uint(f2tf32(vreg[i].x))) : "memory");
            asm volatile("st.shared.b32 [%0], %1;" :: "r"(smb + o1),
                         "r"(__float_as_uint(f2tf32(vreg[i].y))) : "memory");
            asm volatile("st.shared.b32 [%0], %1;" :: "r"(smb + o2),
                         "r"(__float_as_uint(f2tf32(vreg[i].z))) : "memory");
            asm volatile("st.shared.b32 [%0], %1;" :: "r"(smb + o3),
                         "r"(__float_as_uint(f2tf32(vreg[i].w))) : "memory");
        }
        FENCE_PROXY();
        __syncthreads();

        // ---- S = Q.K^T from buffer `buf` ----
        if (tid < 32) {
            if (elect_one()) {
                #pragma unroll
                for (int s = 0; s < 8; s++) {
                    uint64_t ad = make_desc_sw128(smb + AQ_OFF + (s >> 2) * 16384)
                                + (uint64_t)(s & 3) * 2;
                    uint64_t bd = make_desc_sw128(smb + AK_OFF(buf) + (s >> 2) * 16384)
                                + (uint64_t)(s & 3) * 2;
                    mma_tf32_ss(TS, ad, bd, idescS, s != 0);
                }
                TC_COMMIT(mb_s);
            }
        }

        // ---- prefetch KV(t+1) while S-MMA + softmax run ----
        if (t + 1 < 8) {
            #pragma unroll
            for (int i = 0; i < 8; i++) {
                const float* base = qkv + (tokB + (t + 1) * 128 + rI[i]) * QKV_COLS
                                  + h * HDIM + cI[i];
                kreg[i] = *reinterpret_cast<const float4*>(base + DIM);
                vreg[i] = *reinterpret_cast<const float4*>(base + 2 * DIM);
            }
        }

        // ---- softmax in place (batched LDTM, 2 waits) ----
        if (tid < 128) {
            MBAR_WAIT(mb_s, t & 1);
            TC_FENCE_AFTER();
            const uint32_t woff = (uint32_t)(tid >> 5) << 21;
            #pragma unroll
            for (int half = 0; half < 2; half++) {
                uint32_t s0[32], s1[32];
                TMEM_LDX32(s0, TS + half * 64);
                TMEM_LDX32(s1, TS + half * 64 + 32);
                TC_WAIT_LD();
                #pragma unroll
                for (int k = 0; k < 32; k++) {
                    float p = __expf(__uint_as_float(s0[k]));
                    lsum += p;
                    s0[k] = __float_as_uint(f2tf32(p));
                }
                #pragma unroll
                for (int k = 0; k < 32; k++) {
                    float p = __expf(__uint_as_float(s1[k]));
                    lsum += p;
                    s1[k] = __float_as_uint(f2tf32(p));
                }
                TMEM_STX32(TS + half * 64 + woff, s0);
                TMEM_STX32(TS + half * 64 + 32 + woff, s1);
            }
            TC_WAIT_ST();
            TC_FENCE_BEFORE();
        }
        __syncthreads();

        // ---- O += P.V^T from buffer `buf` ----
        if (tid < 32) {
            if (elect_one()) {
                TC_FENCE_AFTER();
                #pragma unroll
                for (int s = 0; s < 16; s++) {
                    uint64_t bd = make_desc_sw128(smb + AV_OFF(buf) + (s >> 2) * 8192)
                                + (uint64_t)(s & 3) * 2;
                    mma_tf32_ts(TO, TS + s * 8, bd, idescO, (t | s) != 0);
                }
                TC_COMMIT(mb_o);
            }
        }
    }

    // ---- epilogue ----
    MBAR_WAIT(mb_o, 7 & 1);
    if (tid < 128) {
        TC_FENCE_AFTER();
        const float inv = 1.f / lsum;
        float* op = out + (tokQ + tid) * (size_t)DIM + h * HDIM;
        uint32_t o0[32], o1[32];
        TMEM_LDX32(o0, TO);
        TMEM_LDX32(o1, TO + 32);
        TC_WAIT_LD();
        #pragma unroll
        for (int c = 0; c < 32; c += 4) {
            float4 v;
            v.x = __uint_as_float(o0[c + 0]) * inv;
            v.y = __uint_as_float(o0[c + 1]) * inv;
            v.z = __uint_as_float(o0[c + 2]) * inv;
            v.w = __uint_as_float(o0[c + 3]) * inv;
            *reinterpret_cast<float4*>(op + c) = v;
        }
        #pragma unroll
        for (int c = 0; c < 32; c += 4) {
            float4 v;
            v.x = __uint_as_float(o1[c + 0]) * inv;
            v.y = __uint_as_float(o1[c + 1]) * inv;
            v.z = __uint_as_float(o1[c + 2]) * inv;
            v.w = __uint_as_float(o1[c + 3]) * inv;
            *reinterpret_cast<float4*>(op + 32 + c) = v;
        }
    }
    __syncthreads();
    if (tid < 32) {
        TC_RELINQ();
        TC_DEALLOC(tmem, 256);
    }
#endif // HAS_TCGEN05
}

// ---------------------------------------------------------------------------
extern "C" void kernel_launch(void* const* d_in, const int* in_sizes, int n_in,
                              void* d_out, int out_size)
{
    const float* inp    = (const float*)d_in[0];   // [8,1024,1024]
    const float* w_qkv  = (const float*)d_in[1];   // [1024,3072]
    const float* b_qkv  = (const float*)d_in[2];   // [3072]
    const float* w_proj = (const float*)d_in[3];   // [1024,1024]
    const float* b_proj = (const float*)d_in[4];   // [1024]
    float* out = (float*)d_out;                    // [8,1024,1024]

    float *qkv_ptr, *att_ptr, *wt_ptr;
    cudaGetSymbolAddress((void**)&qkv_ptr, g_qkv);
    cudaGetSymbolAddress((void**)&att_ptr, g_att);
    cudaGetSymbolAddress((void**)&wt_ptr,  g_wt);
    float* wqkvT  = wt_ptr;                           // [3072][1024]
    float* wprojT = wt_ptr + (size_t)QKV_COLS * DIM;  // [1024][1024]

    cudaFuncSetAttribute(gemm_tc_tf32,
                         cudaFuncAttributeMaxDynamicSharedMemorySize,
                         GEMM_SMEM);
    cudaFuncSetAttribute(attn_tc,
                         cudaFuncAttributeMaxDynamicSharedMemorySize,
                         ATT_SMEM);

    // 0) pre-transpose weights to [N][K] tf32
    {
        dim3 g1(QKV_COLS / 32, DIM / 32);
        transpose_tf32<<<g1, 256>>>(w_qkv, wqkvT, DIM, QKV_COLS);
        dim3 g2(DIM / 32, DIM / 32);
        transpose_tf32<<<g2, 256>>>(w_proj, wprojT, DIM, DIM);
    }
    // 1) QKV GEMM
    {
        dim3 grid(QKV_COLS / BN, M_TOK / BM);
        gemm_tc_tf32<<<grid, 256, GEMM_SMEM>>>(inp, wqkvT, b_qkv, qkv_ptr,
                                               M_TOK, QKV_COLS, DIM);
    }
    // 2) attention
    {
        dim3 grid(SEQ / 128, NHEADS, BATCH);
        attn_tc<<<grid, 256, ATT_SMEM>>>(qkv_ptr, att_ptr);
    }
    // 3) projection
    {
        dim3 grid(DIM / BN, M_TOK / BM);
        gemm_tc_tf32<<<grid, 256, GEMM_SMEM>>>(att_ptr, wprojT, b_proj, out,
                                               M_TOK, DIM, DIM);
    }
}

// round 11
// speedup vs baseline: 1.4037x; 1.0519x over previous
#include <cuda_runtime.h>
#include <cuda_bf16.h>
#include <math.h>
#include <stdint.h>

// Problem constants
#define BATCH 8
#define SEQ 1024
#define DIM 1024
#define NHEADS 16
#define HDIM 64
#define M_TOK (BATCH * SEQ)        // 8192
#define QKV_COLS (3 * DIM)         // 3072
#define ATT_SCALE 0.125f           // 64^-0.5

#if defined(__CUDA_ARCH__) && defined(__CUDA_ARCH_FEAT_SM103_ALL)
#define HAS_TCGEN05 1
#else
#define HAS_TCGEN05 0
#endif

// Scratch (allocation-free rule: __device__ globals)
__device__ float g_qkv[(size_t)M_TOK * QKV_COLS];        // 96 MB
__device__ float g_att[(size_t)M_TOK * DIM];             // 32 MB
__device__ float g_wt[(size_t)(QKV_COLS + DIM) * DIM];   // 16 MB: wqkvT | wprojT

// ===========================================================================
// tcgen05 helpers
// ===========================================================================
__device__ __forceinline__ uint32_t smem_u32(const void* p) {
    uint32_t a;
    asm("{ .reg .u64 t; cvta.to.shared.u64 t, %1; cvt.u32.u64 %0, t; }"
        : "=r"(a) : "l"(p));
    return a;
}

__device__ __forceinline__ uint32_t elect_one() {
    uint32_t pred;
    asm volatile(
        "{\n\t.reg .pred p;\n\t"
        "elect.sync _|p, 0xFFFFFFFF;\n\t"
        "selp.b32 %0, 1, 0, p;\n\t}"
        : "=r"(pred));
    return pred;
}

// SW128 K-major smem descriptor: layout=SW128(2), version=1, SBO=64, LBO=1
__device__ __forceinline__ uint64_t make_desc_sw128(uint32_t addr) {
    const uint64_t base =
        (uint64_t(2) << 61) | (uint64_t(1) << 46) |
        (uint64_t(64) << 32) | (uint64_t(1) << 16);
    return base | ((uint64_t)(addr >> 4) & 0x3FFF);
}

#define SWZ128(off) ((off) ^ (((off) >> 3) & 0x70))

#if HAS_TCGEN05
__device__ __forceinline__ void mma_tf32_ss(uint32_t d, uint64_t ad, uint64_t bd,
                                            uint32_t idesc, uint32_t en) {
    asm volatile(
        "{\n\t.reg .pred p;\n\t"
        "setp.ne.u32 p, %5, 0;\n\t"
        "tcgen05.mma.cta_group::1.kind::tf32 [%0], %1, %2, %3, {%4,%4,%4,%4}, p;\n\t"
        "}"
        :: "r"(d), "l"(ad), "l"(bd), "r"(idesc), "r"(0u), "r"(en)
        : "memory");
}

__device__ __forceinline__ void mma_tf32_ts(uint32_t d, uint32_t at, uint64_t bd,
                                            uint32_t idesc, uint32_t en) {
    asm volatile(
        "{\n\t.reg .pred p;\n\t"
        "setp.ne.u32 p, %5, 0;\n\t"
        "tcgen05.mma.cta_group::1.kind::tf32 [%0], [%1], %2, %3, {%4,%4,%4,%4}, p;\n\t"
        "}"
        :: "r"(d), "r"(at), "l"(bd), "r"(idesc), "r"(0u), "r"(en)
        : "memory");
}

#define TC_ALLOC(sm, n)  asm volatile("tcgen05.alloc.cta_group::1.sync.aligned.shared::cta.b32 [%0], %1;" :: "r"(sm), "r"((uint32_t)(n)) : "memory")
#define TC_DEALLOC(t, n) asm volatile("tcgen05.dealloc.cta_group::1.sync.aligned.b32 %0, %1;" :: "r"(t), "r"((uint32_t)(n)))
#define TC_RELINQ()      asm volatile("tcgen05.relinquish_alloc_permit.cta_group::1.sync.aligned;")
#define TC_COMMIT(mb)    asm volatile("tcgen05.commit.cta_group::1.mbarrier::arrive::one.shared::cluster.b64 [%0];" :: "r"(mb) : "memory")
#define TC_FENCE_BEFORE() asm volatile("tcgen05.fence::before_thread_sync;" ::: "memory")
#define TC_FENCE_AFTER() asm volatile("tcgen05.fence::after_thread_sync;" ::: "memory")
#define TC_WAIT_LD()     asm volatile("tcgen05.wait::ld.sync.aligned;" ::: "memory")
#define TC_WAIT_ST()     asm volatile("tcgen05.wait::st.sync.aligned;" ::: "memory")

#define TMEM_LDX32(r, ta)                                                   \
    asm volatile(                                                           \
        "tcgen05.ld.sync.aligned.32x32b.x32.b32 "                           \
        "{%0,%1,%2,%3,%4,%5,%6,%7,%8,%9,%10,%11,%12,%13,%14,%15,"           \
        "%16,%17,%18,%19,%20,%21,%22,%23,%24,%25,%26,%27,%28,%29,%30,%31}, [%32];" \
        : "=r"((r)[0]),"=r"((r)[1]),"=r"((r)[2]),"=r"((r)[3]),              \
          "=r"((r)[4]),"=r"((r)[5]),"=r"((r)[6]),"=r"((r)[7]),              \
          "=r"((r)[8]),"=r"((r)[9]),"=r"((r)[10]),"=r"((r)[11]),            \
          "=r"((r)[12]),"=r"((r)[13]),"=r"((r)[14]),"=r"((r)[15]),          \
          "=r"((r)[16]),"=r"((r)[17]),"=r"((r)[18]),"=r"((r)[19]),          \
          "=r"((r)[20]),"=r"((r)[21]),"=r"((r)[22]),"=r"((r)[23]),          \
          "=r"((r)[24]),"=r"((r)[25]),"=r"((r)[26]),"=r"((r)[27]),          \
          "=r"((r)[28]),"=r"((r)[29]),"=r"((r)[30]),"=r"((r)[31])           \
        : "r"(ta))

#define TMEM_STX32(ta, r)                                                   \
    asm volatile(                                                           \
        "tcgen05.st.sync.aligned.32x32b.x32.b32 [%0], "                     \
        "{%1,%2,%3,%4,%5,%6,%7,%8,%9,%10,%11,%12,%13,%14,%15,%16,"          \
        "%17,%18,%19,%20,%21,%22,%23,%24,%25,%26,%27,%28,%29,%30,%31,%32};" \
        :: "r"(ta),                                                         \
           "r"((r)[0]),"r"((r)[1]),"r"((r)[2]),"r"((r)[3]),                 \
           "r"((r)[4]),"r"((r)[5]),"r"((r)[6]),"r"((r)[7]),                 \
           "r"((r)[8]),"r"((r)[9]),"r"((r)[10]),"r"((r)[11]),               \
           "r"((r)[12]),"r"((r)[13]),"r"((r)[14]),"r"((r)[15]),             \
           "r"((r)[16]),"r"((r)[17]),"r"((r)[18]),"r"((r)[19]),             \
           "r"((r)[20]),"r"((r)[21]),"r"((r)[22]),"r"((r)[23]),             \
           "r"((r)[24]),"r"((r)[25]),"r"((r)[26]),"r"((r)[27]),             \
           "r"((r)[28]),"r"((r)[29]),"r"((r)[30]),"r"((r)[31])              \
        : "memory")
#endif // HAS_TCGEN05

#define MBAR_INIT(mb, n) asm volatile("mbarrier.init.shared.b64 [%0], %1;" :: "r"(mb), "r"((uint32_t)(n)) : "memory")
#define FENCE_PROXY()    asm volatile("fence.proxy.async.shared::cta;" ::: "memory")

#define MBAR_WAIT(mb, ph) do {                                              \
    uint32_t _m = (mb), _p = (ph), _done;                                   \
    asm volatile(                                                           \
        "{\n\t.reg .pred p;\n\t"                                            \
        "mbarrier.try_wait.parity.acquire.cta.shared::cta.b64 p, [%1], %2;\n\t" \
        "selp.b32 %0, 1, 0, p;\n\t}"                                        \
        : "=r"(_done) : "r"(_m), "r"(_p) : "memory");                       \
    if (!_done) {                                                           \
        asm volatile(                                                       \
            "{\n\t.reg .pred P1;\n\t"                                       \
            "WL_%=:\n\t"                                                    \
            "mbarrier.try_wait.parity.acquire.cta.shared::cta.b64 P1, [%0], %1, 0x989680;\n\t" \
            "@P1 bra.uni WD_%=;\n\t"                                        \
            "bra.uni WL_%=;\n\t"                                            \
            "WD_%=:\n\t}"                                                   \
            :: "r"(_m), "r"(_p) : "memory");                                \
    }                                                                       \
} while (0)

__device__ __forceinline__ float f2tf32(float v) {
    unsigned int u;
    asm volatile("cvt.rna.tf32.f32 %0, %1;" : "=r"(u) : "f"(v));
    return __uint_as_float(u);
}

// ===========================================================================
// Weight pre-transpose: W[K][N] -> WT[N][K], tf32-converted. Run once/launch.
// ===========================================================================
__global__ __launch_bounds__(256) void transpose_tf32(
    const float* __restrict__ W, float* __restrict__ WT, int K, int N)
{
    __shared__ float tile[32][33];
    const int n0 = blockIdx.x * 32;
    const int k0 = blockIdx.y * 32;
    const int tx = threadIdx.x & 31;
    const int ty = threadIdx.x >> 5;

    #pragma unroll
    for (int i = ty; i < 32; i += 8)
        tile[i][tx] = W[(size_t)(k0 + i) * N + n0 + tx];
    __syncthreads();
    #pragma unroll
    for (int i = ty; i < 32; i += 8)
        WT[(size_t)(n0 + i) * K + k0 + tx] = f2tf32(tile[tx][i]);
}

// ===========================================================================
// tcgen05 tf32 GEMM (pre-transposed B) — proven round-7 configuration.
// ===========================================================================
#define BM 128
#define BN 128
#define GBK 64
#define GA0 0
#define GA1 32768
#define GB0 65536
#define GB1 98304
#define GEMM_SMEM 131072

__global__ __launch_bounds__(256, 1) __cluster_dims__(1, 1, 1)
void gemm_tc_tf32(const float* __restrict__ A, const float* __restrict__ BT,
                  const float* __restrict__ bias, float* __restrict__ C,
                  int M, int N, int K)
{
#if HAS_TCGEN05
    extern __shared__ __align__(1024) char dsm[];
    __shared__ uint32_t s_tmem;
    __shared__ __align__(8) uint64_t s_mbar[2];

    const int tid = threadIdx.x;
    const int brow = blockIdx.y * BM;
    const int bcol = blockIdx.x * BN;
    const uint32_t smb = smem_u32(dsm);
    const uint32_t mbar0 = smem_u32(&s_mbar[0]);
    const uint32_t mbar1 = smem_u32(&s_mbar[1]);

    if (tid < 32) TC_ALLOC(smem_u32(&s_tmem), 128);
    if (tid == 0) { MBAR_INIT(mbar0, 1); MBAR_INIT(mbar1, 1); }
    __syncthreads();
    const uint32_t tmem = s_tmem;

    const uint32_t idesc = (1u << 4) | (2u << 7) | (2u << 10)
                         | ((BN / 8) << 17) | ((BM / 16) << 24);
    const int nch = K / GBK;   // 16

    int rr[8], cc[8];
    uint32_t soff[8];
    #pragma unroll
    for (int i = 0; i < 8; i++) {
        int id = i * 256 + tid;
        int r = id >> 4;
        int c = (id & 15) * 4;
        rr[i] = r; cc[i] = c;
        uint32_t off = (uint32_t)(((c >> 5) * 16 + (r >> 3)) * 1024
                                  + (r & 7) * 128 + (c & 31) * 4);
        soff[i] = SWZ128(off);
    }

    float4 av[8], bv[8];
    #pragma unroll
    for (int i = 0; i < 8; i++) {
        av[i] = *reinterpret_cast<const float4*>(
            A + (size_t)(brow + rr[i]) * K + cc[i]);
        bv[i] = *reinterpret_cast<const float4*>(
            BT + (size_t)(bcol + rr[i]) * K + cc[i]);
    }

    for (int ch = 0; ch < nch; ch++) {
        const int b = ch & 1;
        const uint32_t abuf = smb + (b ? GA1 : GA0);
        const uint32_t bbuf = smb + (b ? GB1 : GB0);

        if (ch >= 2) MBAR_WAIT(b ? mbar1 : mbar0, ((ch >> 1) - 1) & 1);

        #pragma unroll
        for (int i = 0; i < 8; i++) {
            asm volatile("st.shared.v4.b32 [%0], {%1,%2,%3,%4};"
                :: "r"(abuf + soff[i]),
                   "r"(__float_as_uint(f2tf32(av[i].x))),
                   "r"(__float_as_uint(f2tf32(av[i].y))),
                   "r"(__float_as_uint(f2tf32(av[i].z))),
                   "r"(__float_as_uint(f2tf32(av[i].w))) : "memory");
            asm volatile("st.shared.v4.b32 [%0], {%1,%2,%3,%4};"
                :: "r"(bbuf + soff[i]),
                   "r"(__float_as_uint(bv[i].x)), "r"(__float_as_uint(bv[i].y)),
                   "r"(__float_as_uint(bv[i].z)), "r"(__float_as_uint(bv[i].w))
                : "memory");
        }

        if (ch + 1 < nch) {
            const int k0 = (ch + 1) * GBK;
            #pragma unroll
            for (int i = 0; i < 8; i++) {
                av[i] = *reinterpret_cast<const float4*>(
                    A + (size_t)(brow + rr[i]) * K + k0 + cc[i]);
                bv[i] = *reinterpret_cast<const float4*>(
                    BT + (size_t)(bcol + rr[i]) * K + k0 + cc[i]);
            }
        }

        FENCE_PROXY();
        __syncthreads();

        if (tid < 32) {
            if (elect_one()) {
                uint64_t ad = make_desc_sw128(abuf);
                uint64_t bd = make_desc_sw128(bbuf);
                #pragma unroll
                for (int s = 0; s < 8; s++) {
                    uint64_t dso = (uint64_t)((s & 3) * 2 + (s >> 2) * 1024);
                    mma_tf32_ss(tmem, ad + dso, bd + dso, idesc, (ch | s) != 0);
                }
                TC_COMMIT(b ? mbar1 : mbar0);
            }
        }
    }

    {
        const int last = nch - 1;
        MBAR_WAIT((last & 1) ? mbar1 : mbar0, (last >> 1) & 1);
    }
    TC_FENCE_AFTER();

    if (tid < 128) {
        const int wid = tid >> 5;
        const int lane = tid & 31;
        const int row = brow + wid * 32 + lane;
        #pragma unroll
        for (int c0 = 0; c0 < BN; c0 += 32) {
            uint32_t d[32];
            TMEM_LDX32(d, tmem + c0);
            TC_WAIT_LD();
            #pragma unroll
            for (int c = 0; c < 32; c += 4) {
                float4 v;
                v.x = __uint_as_float(d[c + 0]) + bias[bcol + c0 + c + 0];
                v.y = __uint_as_float(d[c + 1]) + bias[bcol + c0 + c + 1];
                v.z = __uint_as_float(d[c + 2]) + bias[bcol + c0 + c + 2];
                v.w = __uint_as_float(d[c + 3]) + bias[bcol + c0 + c + 3];
                *reinterpret_cast<float4*>(C + (size_t)row * N + bcol + c0 + c) = v;
            }
        }
    }
    __syncthreads();
    if (tid < 32) {
        TC_RELINQ();
        TC_DEALLOC(tmem, 128);
    }
#endif // HAS_TCGEN05
}

// ===========================================================================
// Tensor-core flash attention (tf32, no online max), fully pipelined:
//  - K/V stores of tile t overlap O-MMA(t-1) (mb_o wait moved to S-MMA issue)
//  - softmax + epilogue split across all 256 threads (wg0: cols 0-63,
//    wg1: cols 64-127; same TMEM lanes). lsum combined via smem.
// TMEM (256 cols): S/P in place cols [0,128), O cols [128,192).
// SMEM 160KB: Q 32K | K0 32K | K1 32K | Vt0 32K | Vt1 32K.
// ===========================================================================
#define AQ_OFF 0
#define AK_OFF(buf) (32768 + (buf) * 32768)
#define AV_OFF(buf) (98304 + (buf) * 32768)
#define ATT_SMEM 163840

__global__ __launch_bounds__(256, 1) __cluster_dims__(1, 1, 1)
void attn_tc(const float* __restrict__ qkv, float* __restrict__ out)
{
#if HAS_TCGEN05
    extern __shared__ __align__(1024) char dsm[];
    __shared__ uint32_t s_tmem;
    __shared__ __align__(8) uint64_t s_mb[2];
    __shared__ float s_l[256];

    const int tid = threadIdx.x;
    const int qt = blockIdx.x;
    const int h  = blockIdx.y;
    const int b  = blockIdx.z;
    const uint32_t smb = smem_u32(dsm);
    const uint32_t mb_s = smem_u32(&s_mb[0]);
    const uint32_t mb_o = smem_u32(&s_mb[1]);

    if (tid < 32) TC_ALLOC(smem_u32(&s_tmem), 256);
    if (tid == 0) { MBAR_INIT(mb_s, 1); MBAR_INIT(mb_o, 1); }
    __syncthreads();
    const uint32_t tmem = s_tmem;
    const uint32_t TS = tmem;            // S cols [0,128); P in place
    const uint32_t TO = tmem + 128;      // O cols [128,192)

    const size_t tokQ = (size_t)b * SEQ + qt * 128;
    const size_t tokB = (size_t)b * SEQ;

    const uint32_t idescS = (1u << 4) | (2u << 7) | (2u << 10)
                          | (16u << 17) | (8u << 24);
    const uint32_t idescO = (1u << 4) | (2u << 7) | (2u << 10)
                          | (8u << 17) | (8u << 24);

    int rI[8], cI[8];
    #pragma unroll
    for (int i = 0; i < 8; i++) {
        int id = i * 256 + tid;
        rI[i] = id >> 4;            // row/key 0..127
        cI[i] = (id & 15) * 4;      // dim 0..60
    }

    // ---- Q tile -> smem (scaled, tf32) ----
    #pragma unroll
    for (int i = 0; i < 8; i++) {
        float4 v = *reinterpret_cast<const float4*>(
            qkv + (tokQ + rI[i]) * QKV_COLS + h * HDIM + cI[i]);
        uint32_t off = AQ_OFF + (cI[i] >> 5) * 16384
                     + SWZ128((uint32_t)(rI[i] * 128 + (cI[i] & 31) * 4));
        asm volatile("st.shared.v4.b32 [%0], {%1,%2,%3,%4};"
            :: "r"(smb + off),
               "r"(__float_as_uint(f2tf32(v.x * ATT_SCALE))),
               "r"(__float_as_uint(f2tf32(v.y * ATT_SCALE))),
               "r"(__float_as_uint(f2tf32(v.z * ATT_SCALE))),
               "r"(__float_as_uint(f2tf32(v.w * ATT_SCALE))) : "memory");
    }

    // ---- prefetch KV tile 0 into registers ----
    float4 kreg[8], vreg[8];
    #pragma unroll
    for (int i = 0; i < 8; i++) {
        const float* base = qkv + (tokB + rI[i]) * QKV_COLS + h * HDIM + cI[i];
        kreg[i] = *reinterpret_cast<const float4*>(base + DIM);
        vreg[i] = *reinterpret_cast<const float4*>(base + 2 * DIM);
    }

    float lsum = 0.f;

    for (int t = 0; t < 8; t++) {
        const int buf = t & 1;

        // ---- store prefetched K/V regs into smem buffer `buf`.
        // These overlap O-MMA(t-1): it reads V buffer buf^1 and TS only.
        #pragma unroll
        for (int i = 0; i < 8; i++) {
            uint32_t koff = AK_OFF(buf) + (cI[i] >> 5) * 16384
                          + SWZ128((uint32_t)(rI[i] * 128 + (cI[i] & 31) * 4));
            asm volatile("st.shared.v4.b32 [%0], {%1,%2,%3,%4};"
                :: "r"(smb + koff),
                   "r"(__float_as_uint(f2tf32(kreg[i].x))),
                   "r"(__float_as_uint(f2tf32(kreg[i].y))),
                   "r"(__float_as_uint(f2tf32(kreg[i].z))),
                   "r"(__float_as_uint(f2tf32(kreg[i].w))) : "memory");
            uint32_t kb  = (rI[i] >> 5) * 8192;
            uint32_t kc4 = (rI[i] & 31) * 4;
            uint32_t o0 = AV_OFF(buf) + kb + SWZ128((uint32_t)((cI[i] + 0) * 128 + kc4));
            uint32_t o1 = AV_OFF(buf) + kb + SWZ128((uint32_t)((cI[i] + 1) * 128 + kc4));
            uint32_t o2 = AV_OFF(buf) + kb + SWZ128((uint32_t)((cI[i] + 2) * 128 + kc4));
            uint32_t o3 = AV_OFF(buf) + kb + SWZ128((uint32_t)((cI[i] + 3) * 128 + kc4));
            asm volatile("st.shared.b32 [%0], %1;" :: "r"(smb + o0),
                         "r"(__float_as_uint(f2tf32(vreg[i].x))) : "memory");
            asm volatile("st.shared.b32 [%0], %1;" :: "r"(smb + o1),
                         "r"(__float_as_uint(f2tf32(vreg[i].y))) : "memory");
            asm volatile("st.shared.b32 [%0], %1;" :: "r"(smb + o2),
                         "r"(__float_as_uint(f2tf32(vreg[i].z))) : "memory");
            asm volatile("st.shared.b32 [%0], %1;" :: "r"(smb + o3),
                         "r"(__float_as_uint(f2tf32(vreg[i].w))) : "memory");
        }
        FENCE_PROXY();
        __syncthreads();

        // ---- S = Q.K^T; warp 0 first waits for O-MMA(t-1) (TS/P hazard) ----
        if (tid < 32) {
            if (t > 0) MBAR_WAIT(mb_o, (t - 1) & 1);
            if (elect_one()) {
                #pragma unroll
                for (int s = 0; s < 8; s++) {
                    uint64_t ad = make_desc_sw128(smb + AQ_OFF + (s >> 2) * 16384)
                                + (uint64_t)(s & 3) * 2;
                    uint64_t bd = make_desc_sw128(smb + AK_OFF(buf) + (s >> 2) * 16384)
                                + (uint64_t)(s & 3) * 2;
                    mma_tf32_ss(TS, ad, bd, idescS, s != 0);
                }
                TC_COMMIT(mb_s);
            }
        }

        // ---- prefetch KV(t+1) while S-MMA + softmax run ----
        if (t + 1 < 8) {
            #pragma unroll
            for (int i = 0; i < 8; i++) {
                const float* base = qkv + (tokB + (t + 1) * 128 + rI[i]) * QKV_COLS
                                  + h * HDIM + cI[i];
                kreg[i] = *reinterpret_cast<const float4*>(base + DIM);
                vreg[i] = *reinterpret_cast<const float4*>(base + 2 * DIM);
            }
        }

        // ---- softmax in place, ALL 256 threads (wg0: cols 0-63, wg1: 64-127)
        {
            MBAR_WAIT(mb_s, t & 1);
            TC_FENCE_AFTER();
            const int wg = tid >> 7;
            const uint32_t cbase = TS + wg * 64;
            const uint32_t woff = (uint32_t)((tid & 127) >> 5) << 21;
            uint32_t s0[32], s1[32];
            TMEM_LDX32(s0, cbase);
            TMEM_LDX32(s1, cbase + 32);
            TC_WAIT_LD();
            #pragma unroll
            for (int k = 0; k < 32; k++) {
                float p = __expf(__uint_as_float(s0[k]));
                lsum += p;
                s0[k] = __float_as_uint(f2tf32(p));
            }
            #pragma unroll
            for (int k = 0; k < 32; k++) {
                float p = __expf(__uint_as_float(s1[k]));
                lsum += p;
                s1[k] = __float_as_uint(f2tf32(p));
            }
            TMEM_STX32(cbase + woff, s0);
            TMEM_STX32(cbase + 32 + woff, s1);
            TC_WAIT_ST();
            TC_FENCE_BEFORE();
        }
        __syncthreads();

        // ---- O += P.V^T from buffer `buf` ----
        if (tid < 32) {
            if (elect_one()) {
                TC_FENCE_AFTER();
                #pragma unroll
                for (int s = 0; s < 16; s++) {
                    uint64_t bd = make_desc_sw128(smb + AV_OFF(buf) + (s >> 2) * 8192)
                                + (uint64_t)(s & 3) * 2;
                    mma_tf32_ts(TO, TS + s * 8, bd, idescO, (t | s) != 0);
                }
                TC_COMMIT(mb_o);
            }
        }
    }

    // ---- epilogue: combine lsum across warpgroups, write split halves ----
    s_l[tid] = lsum;
    __syncthreads();
    MBAR_WAIT(mb_o, 7 & 1);
    TC_FENCE_AFTER();
    {
        const int row = tid & 127;
        const int wg  = tid >> 7;
        const float inv = 1.f / (s_l[row] + s_l[128 + row]);
        uint32_t o0[32];
        TMEM_LDX32(o0, TO + wg * 32);
        TC_WAIT_LD();
        float* op = out + (tokQ + row) * (size_t)DIM + h * HDIM + wg * 32;
        #pragma unroll
        for (int c = 0; c < 32; c += 4) {
            float4 v;
            v.x = __uint_as_float(o0[c + 0]) * inv;
            v.y = __uint_as_float(o0[c + 1]) * inv;
            v.z = __uint_as_float(o0[c + 2]) * inv;
            v.w = __uint_as_float(o0[c + 3]) * inv;
            *reinterpret_cast<float4*>(op + c) = v;
        }
    }
    __syncthreads();
    if (tid < 32) {
        TC_RELINQ();
        TC_DEALLOC(tmem, 256);
    }
#endif // HAS_TCGEN05
}

// ---------------------------------------------------------------------------
extern "C" void kernel_launch(void* const* d_in, const int* in_sizes, int n_in,
                              void* d_out, int out_size)
{
    const float* inp    = (const float*)d_in[0];   // [8,1024,1024]
    const float* w_qkv  = (const float*)d_in[1];   // [1024,3072]
    const float* b_qkv  = (const float*)d_in[2];   // [3072]
    const float* w_proj = (const float*)d_in[3];   // [1024,1024]
    const float* b_proj = (const float*)d_in[4];   // [1024]
    float* out = (float*)d_out;                    // [8,1024,1024]

    float *qkv_ptr, *att_ptr, *wt_ptr;
    cudaGetSymbolAddress((void**)&qkv_ptr, g_qkv);
    cudaGetSymbolAddress((void**)&att_ptr, g_att);
    cudaGetSymbolAddress((void**)&wt_ptr,  g_wt);
    float* wqkvT  = wt_ptr;                           // [3072][1024]
    float* wprojT = wt_ptr + (size_t)QKV_COLS * DIM;  // [1024][1024]

    cudaFuncSetAttribute(gemm_tc_tf32,
                         cudaFuncAttributeMaxDynamicSharedMemorySize,
                         GEMM_SMEM);
    cudaFuncSetAttribute(attn_tc,
                         cudaFuncAttributeMaxDynamicSharedMemorySize,
                         ATT_SMEM);

    // 0) pre-transpose weights to [N][K] tf32
    {
        dim3 g1(QKV_COLS / 32, DIM / 32);
        transpose_tf32<<<g1, 256>>>(w_qkv, wqkvT, DIM, QKV_COLS);
        dim3 g2(DIM / 32, DIM / 32);
        transpose_tf32<<<g2, 256>>>(w_proj, wprojT, DIM, DIM);
    }
    // 1) QKV GEMM
    {
        dim3 grid(QKV_COLS / BN, M_TOK / BM);
        gemm_tc_tf32<<<grid, 256, GEMM_SMEM>>>(inp, wqkvT, b_qkv, qkv_ptr,
                                               M_TOK, QKV_COLS, DIM);
    }
    // 2) attention
    {
        dim3 grid(SEQ / 128, NHEADS, BATCH);
        attn_tc<<<grid, 256, ATT_SMEM>>>(qkv_ptr, att_ptr);
    }
    // 3) projection
    {
        dim3 grid(DIM / BN, M_TOK / BM);
        gemm_tc_tf32<<<grid, 256, GEMM_SMEM>>>(att_ptr, wprojT, b_proj, out,
                                               M_TOK, DIM, DIM);
    }
}